// round 6
// baseline (speedup 1.0000x reference)
#include <cuda_runtime.h>
#include <cuda_bf16.h>
#include <math.h>

// Problem constants
#define B   256
#define S   512
#define H   256
#define OUT 3
#define NSTEP 64
#define G4  1024          // 4*H
#define INW 259           // OUT + H
#define KP  528           // padded K (515 -> 33 tiles of 16)
#define NSPLIT 8

#define PRED_SZ (B*NSTEP*OUT)          // 49152
#define HID_OFF PRED_SZ                // 49152
#define ATTN_OFF (PRED_SZ + B*H)       // 114688

// ---------------- scratch (device globals; no allocation) ----------------
__device__ float g_P[H*H];         // P row-major: P[h*H + j] = sum_g Ua[g,h]*Wa[g,j]
__device__ float g_q[H];           // Ua^T @ ba
__device__ float g_Wc[KP*G4];      // packed weights, k-major: Wc[k*1024 + r]
__device__ float g_bias[G4];       // b_ih + b_hh
__device__ float g_XT[KP*B];       // X^T: rows 0..255 ctx, 256..511 h, 512..514 x_in, rest 0
__device__ float g_c[B*H];         // cell state
__device__ float g_gates[NSPLIT][B*G4]; // K-split partial gate buffers, layout [b*1024 + r]

// ---------------- helpers ----------------
__device__ __forceinline__ float sigmoidf_(float x){ return 1.f/(1.f+expf(-x)); }
__device__ __forceinline__ float dot4(float4 a, float4 b){
    return a.x*b.x + a.y*b.y + a.z*b.z + a.w*b.w;
}
__device__ __forceinline__ void cpasync16(void* sdst, const void* gsrc){
    unsigned sa = (unsigned)__cvta_generic_to_shared(sdst);
    asm volatile("cp.async.cg.shared.global [%0], [%1], 16;\n" :: "r"(sa), "l"(gsrc) : "memory");
}
__device__ __forceinline__ void cp_commit(){ asm volatile("cp.async.commit_group;\n" ::: "memory"); }
__device__ __forceinline__ void cp_wait2(){ asm volatile("cp.async.wait_group 2;\n" ::: "memory"); }

// ---------------- precompute 1a: P (row-major) ----------------
__global__ void __launch_bounds__(256) prep_pt(const float* __restrict__ Wa,
                                               const float* __restrict__ Ua){
    int j = blockIdx.x, h = threadIdx.x;
    float acc = 0.f;
    for (int g = 0; g < H; g++) acc += Ua[g*H + h] * Wa[g*H + j];
    g_P[h*H + j] = acc;
}

// ---------------- precompute 1b: q ----------------
__global__ void __launch_bounds__(256) prep_vec(const float* __restrict__ ba,
                                                const float* __restrict__ Ua){
    int h = threadIdx.x;
    float a = 0.f;
    for (int g = 0; g < H; g++) a += Ua[g*H + h] * ba[g];
    g_q[h] = a;
}

// ---------------- precompute 2: pack weights + bias + zero pads ----------------
__global__ void __launch_bounds__(256) prep_pack(const float* __restrict__ W_ih,
                                                 const float* __restrict__ W_hh,
                                                 const float* __restrict__ b_ih,
                                                 const float* __restrict__ b_hh){
    int k = blockIdx.x, t = threadIdx.x;
    #pragma unroll
    for (int m = 0; m < 4; m++){
        int r = t + m*256;
        float v;
        if (k < 256)      v = W_ih[r*INW + 3 + k];       // ctx part
        else if (k < 512) v = W_hh[r*H + (k - 256)];     // h part
        else if (k < 515) v = W_ih[r*INW + (k - 512)];   // x_in part
        else              v = 0.f;                       // pad
        g_Wc[k*G4 + r] = v;
    }
    if (k >= 515) g_XT[k*B + t] = 0.f;                   // zero pad rows of X^T
    if (k < 4){
        int r = k*256 + t;
        g_bias[r] = b_ih[r] + b_hh[r];
    }
}

// ---------------- ATT kernel ----------------
// grid = 256 (one block per batch), 256 threads = 8 warps, 2 blocks/SM.
// Per-warp cp.async ring (3 x 4KB), depth-2 in flight. Each lane reads ONLY
// the bytes it copied itself -> per-thread wait_group suffices, no barriers
// in the streaming loop.
// dynamic smem (floats):
//   buf    [8 warps][3][1024]  : 24576
//   scores [512]               : 24576
//   ctxbuf [8*256]             : 25088
//   hsm    [256]               : 27136
//   vqsm   [256]               : 27392
//   red    [32]                : 27648
//   mbuf   [8]                 : 27680
//   dbuf   [8]                 : 27688
// total 27696 floats = 110784 bytes
#define ATT_SMEM_FLOATS 27696
#define ATT_SMEM_BYTES (ATT_SMEM_FLOATS*4)

__global__ void __launch_bounds__(256, 2) att_step(const float* __restrict__ enc,
                                                   const float* __restrict__ eh,
                                                   const float* __restrict__ ec,
                                                   const float* __restrict__ Wo,
                                                   const float* __restrict__ bo,
                                                   float* __restrict__ out,
                                                   int step, int last){
    extern __shared__ float sm[];
    float* buf    = sm;
    float* scores = sm + 24576;
    float* ctxbuf = sm + 25088;
    float* hsm    = sm + 27136;
    float* vqsm   = sm + 27392;
    float* red    = sm + 27648;
    float* mbuf   = sm + 27680;
    float* dbuf   = sm + 27688;

    const int tid  = threadIdx.x;
    const int w    = tid >> 5;           // warp 0..7
    const int lane = tid & 31;
    const int b    = blockIdx.x;

    // per-warp stream pointers (rows [w*64, w*64+64))
    const float4* encw = (const float4*)(enc + (size_t)b*S*H + (size_t)(w*64)*H);
    float* wbuf = buf + w*3072;          // 3 slots x 1024 floats

    // ---- prologue: issue chunks 0,1 (hidden behind LSTM/pred/vq phases) ----
    if (!last){
        #pragma unroll
        for (int ch = 0; ch < 2; ch++){
            const float4* src = encw + ch*256;           // 4 rows = 256 float4
            float4* dst = (float4*)(wbuf + ch*1024);
            #pragma unroll
            for (int i = 0; i < 8; i++) cpasync16(dst + i*32 + lane, src + i*32 + lane);
            cp_commit();
        }
    }

    // ---- Phase 0: LSTM cell ----
    float h;
    if (step == 0){
        h = eh[b*H + tid];
        g_c[b*H + tid] = ec[b*H + tid];
        if (tid < 3) g_XT[(512 + tid)*B + b] = 0.f;   // x_in = SOS = 0
    } else {
        float zi = 0.f, zf = 0.f, zg = 0.f, zo = 0.f;
        #pragma unroll
        for (int z = 0; z < NSPLIT; z++){
            const float* G = g_gates[z] + b*G4 + tid;
            zi += G[0]; zf += G[256]; zg += G[512]; zo += G[768];
        }
        float co = g_c[b*H + tid];
        float cn = sigmoidf_(zf)*co + sigmoidf_(zi)*tanhf(zg);
        h = sigmoidf_(zo)*tanhf(cn);
        g_c[b*H + tid] = cn;
    }
    hsm[tid] = h;
    if (!last) g_XT[(256 + tid)*B + b] = h;
    __syncthreads();

    // ---- pred = Wo @ h + bo  (previous step's output; feeds x_in) ----
    if (step > 0){
        float v0 = Wo[tid] * h, v1 = Wo[256 + tid] * h, v2 = Wo[512 + tid] * h;
        #pragma unroll
        for (int o = 16; o > 0; o >>= 1){
            v0 += __shfl_down_sync(0xffffffffu, v0, o);
            v1 += __shfl_down_sync(0xffffffffu, v1, o);
            v2 += __shfl_down_sync(0xffffffffu, v2, o);
        }
        if (lane == 0){ red[w] = v0; red[8 + w] = v1; red[16 + w] = v2; }
        __syncthreads();
        if (tid == 0){
            float a0 = 0.f, a1 = 0.f, a2 = 0.f;
            #pragma unroll
            for (int i = 0; i < 8; i++){ a0 += red[i]; a1 += red[8+i]; a2 += red[16+i]; }
            float p0 = a0 + bo[0], p1 = a1 + bo[1], p2 = a2 + bo[2];
            size_t po = (size_t)b*(NSTEP*OUT) + (step - 1)*OUT;
            out[po] = p0; out[po+1] = p1; out[po+2] = p2;
            if (!last){
                g_XT[512*B + b] = p0;
                g_XT[513*B + b] = p1;
                g_XT[514*B + b] = p2;
            }
        }
    }

    if (last){
        out[HID_OFF + b*H + tid] = h;   // decoder_hidden
        return;
    }

    // ---- vq = P @ h + q  (per-thread row of P, vectorized LDG.128) ----
    {
        float a0 = g_q[tid], a1 = 0.f, a2 = 0.f, a3 = 0.f;
        const float4* Pr = (const float4*)(g_P + tid*H);
        const float4* hv4 = (const float4*)hsm;
        #pragma unroll 8
        for (int j4 = 0; j4 < 64; j4 += 4){
            a0 += dot4(Pr[j4],   hv4[j4]);
            a1 += dot4(Pr[j4+1], hv4[j4+1]);
            a2 += dot4(Pr[j4+2], hv4[j4+2]);
            a3 += dot4(Pr[j4+3], hv4[j4+3]);
        }
        vqsm[tid] = (a0 + a1) + (a2 + a3);
    }
    __syncthreads();

    // per-lane vq registers: elems 4*lane..+3 and 128+4*lane..+3
    const float4 vqa = *(const float4*)&vqsm[4*lane];
    const float4 vqb = *(const float4*)&vqsm[128 + 4*lane];

    // ---- streaming loop: 16 chunks x 4 rows, per-warp cp.async ring ----
    float m = -1e30f, d = 0.f;
    float4 ctxa = make_float4(0.f,0.f,0.f,0.f);
    float4 ctxb = make_float4(0.f,0.f,0.f,0.f);

    for (int c = 0; c < 16; c++){
        // issue chunk c+2 into slot (c+2)%3 (empty commit keeps group count uniform)
        if (c + 2 < 16){
            const float4* src = encw + (c+2)*256;
            float4* dst = (float4*)(wbuf + ((c+2)%3)*1024);
            #pragma unroll
            for (int i = 0; i < 8; i++) cpasync16(dst + i*32 + lane, src + i*32 + lane);
        }
        cp_commit();
        cp_wait2();    // chunk c complete (this thread's own bytes)

        const float4* eb = (const float4*)(wbuf + (c%3)*1024);
        float4 A0 = eb[lane],           B0 = eb[32 + lane];
        float4 A1 = eb[64 + lane],      B1 = eb[96 + lane];
        float4 A2 = eb[128 + lane],     B2 = eb[160 + lane];
        float4 A3 = eb[192 + lane],     B3 = eb[224 + lane];

        float p0 = dot4(A0, vqa) + dot4(B0, vqb);
        float p1 = dot4(A1, vqa) + dot4(B1, vqb);
        float p2 = dot4(A2, vqa) + dot4(B2, vqb);
        float p3 = dot4(A3, vqa) + dot4(B3, vqb);
        #pragma unroll
        for (int o = 16; o > 0; o >>= 1){
            p0 += __shfl_xor_sync(0xffffffffu, p0, o);
            p1 += __shfl_xor_sync(0xffffffffu, p1, o);
            p2 += __shfl_xor_sync(0xffffffffu, p2, o);
            p3 += __shfl_xor_sync(0xffffffffu, p3, o);
        }
        if (lane == 0) *(float4*)&scores[w*64 + c*4] = make_float4(p0, p1, p2, p3);

        float mn = fmaxf(m, fmaxf(fmaxf(p0, p1), fmaxf(p2, p3)));
        float rs = __expf(m - mn);
        float e0 = __expf(p0 - mn);
        float e1 = __expf(p1 - mn);
        float e2 = __expf(p2 - mn);
        float e3 = __expf(p3 - mn);
        d = d*rs + (e0 + e1) + (e2 + e3);
        ctxa.x = ctxa.x*rs + e0*A0.x + e1*A1.x + e2*A2.x + e3*A3.x;
        ctxa.y = ctxa.y*rs + e0*A0.y + e1*A1.y + e2*A2.y + e3*A3.y;
        ctxa.z = ctxa.z*rs + e0*A0.z + e1*A1.z + e2*A2.z + e3*A3.z;
        ctxa.w = ctxa.w*rs + e0*A0.w + e1*A1.w + e2*A2.w + e3*A3.w;
        ctxb.x = ctxb.x*rs + e0*B0.x + e1*B1.x + e2*B2.x + e3*B3.x;
        ctxb.y = ctxb.y*rs + e0*B0.y + e1*B1.y + e2*B2.y + e3*B3.y;
        ctxb.z = ctxb.z*rs + e0*B0.z + e1*B1.z + e2*B2.z + e3*B3.z;
        ctxb.w = ctxb.w*rs + e0*B0.w + e1*B1.w + e2*B2.w + e3*B3.w;
        m = mn;
    }

    // ---- merge 8 warp-private states ----
    *(float4*)&ctxbuf[w*H + 4*lane]       = ctxa;
    *(float4*)&ctxbuf[w*H + 128 + 4*lane] = ctxb;
    if (lane == 0){ mbuf[w] = m; dbuf[w] = d; }
    __syncthreads();

    float M = -1e30f;
    #pragma unroll
    for (int i = 0; i < 8; i++) M = fmaxf(M, mbuf[i]);
    float D = 0.f;
    float ew[8];
    #pragma unroll
    for (int i = 0; i < 8; i++){ ew[i] = __expf(mbuf[i] - M); D += dbuf[i] * ew[i]; }
    float inv = 1.f / D;

    {
        float cx = 0.f;
        #pragma unroll
        for (int i = 0; i < 8; i++) cx += ctxbuf[i*H + tid] * ew[i];
        g_XT[tid*B + b] = cx * inv;
    }
    size_t abase = (size_t)ATTN_OFF + ((size_t)b*NSTEP + step)*S;
    out[abase + tid]       = __expf(scores[tid]       - M) * inv;
    out[abase + tid + 256] = __expf(scores[tid + 256] - M) * inv;
}

// ---------------- gates GEMM: C[r,b] = sum_k Wc[k,r] * XT[k,b], 8-way K split ----------------
// grid (16, 4, 8): 64x64 output tiles, z = K split. 256 threads, 4x4 microtile.
__global__ void __launch_bounds__(256) gates_gemm(){
    const int rt = blockIdx.x, bt = blockIdx.y, z = blockIdx.z;
    const int starts[9] = {0, 5, 9, 13, 17, 21, 25, 29, 33};
    const int t0 = starts[z], t1 = starts[z+1];

    __shared__ float As[2][16][68];
    __shared__ float Bs[2][16][68];

    const int tid = threadIdx.x;
    const int tx = tid & 15, ty = tid >> 4;
    const int lk = tid >> 4, lx = (tid & 15) * 4;

    float4 pa, pb;
    {
        int k = t0*16 + lk;
        pa = *(const float4*)&g_Wc[k*G4 + rt*64 + lx];
        pb = *(const float4*)&g_XT[k*B  + bt*64 + lx];
    }
    *(float4*)&As[0][lk][lx] = pa;
    *(float4*)&Bs[0][lk][lx] = pb;

    float acc[4][4];
    #pragma unroll
    for (int i = 0; i < 4; i++)
        #pragma unroll
        for (int j = 0; j < 4; j++) acc[i][j] = 0.f;

    const int nt = t1 - t0;
    for (int it = 0; it < nt; it++){
        __syncthreads();
        if (it + 1 < nt){
            int k = (t0 + it + 1)*16 + lk;
            pa = *(const float4*)&g_Wc[k*G4 + rt*64 + lx];
            pb = *(const float4*)&g_XT[k*B  + bt*64 + lx];
        }
        int cur = it & 1;
        #pragma unroll
        for (int kk = 0; kk < 16; kk++){
            float4 fa = *(float4*)&As[cur][kk][ty*4];
            float4 fb = *(float4*)&Bs[cur][kk][tx*4];
            acc[0][0] += fa.x*fb.x; acc[0][1] += fa.x*fb.y; acc[0][2] += fa.x*fb.z; acc[0][3] += fa.x*fb.w;
            acc[1][0] += fa.y*fb.x; acc[1][1] += fa.y*fb.y; acc[1][2] += fa.y*fb.z; acc[1][3] += fa.y*fb.w;
            acc[2][0] += fa.z*fb.x; acc[2][1] += fa.z*fb.y; acc[2][2] += fa.z*fb.z; acc[2][3] += fa.z*fb.w;
            acc[3][0] += fa.w*fb.x; acc[3][1] += fa.w*fb.y; acc[3][2] += fa.w*fb.z; acc[3][3] += fa.w*fb.w;
        }
        if (it + 1 < nt){
            int nxt = cur ^ 1;
            *(float4*)&As[nxt][lk][lx] = pa;
            *(float4*)&Bs[nxt][lk][lx] = pb;
        }
    }

    float* G = g_gates[z];
    const int r0 = rt*64 + ty*4;
    const int b0 = bt*64 + tx*4;
    #pragma unroll
    for (int j = 0; j < 4; j++){
        float4 v = make_float4(acc[0][j], acc[1][j], acc[2][j], acc[3][j]);
        if (z == 0){
            v.x += g_bias[r0];     v.y += g_bias[r0 + 1];
            v.z += g_bias[r0 + 2]; v.w += g_bias[r0 + 3];
        }
        *(float4*)&G[(size_t)(b0 + j)*G4 + r0] = v;
    }
}

// ---------------- launch ----------------
extern "C" void kernel_launch(void* const* d_in, const int* in_sizes, int n_in,
                              void* d_out, int out_size){
    const float* enc = (const float*)d_in[0];
    const float* eh  = (const float*)d_in[1];
    const float* ec  = (const float*)d_in[2];
    const float* Wa  = (const float*)d_in[3];
    const float* ba  = (const float*)d_in[4];
    const float* Ua  = (const float*)d_in[5];
    const float* Wih = (const float*)d_in[7];
    const float* Whh = (const float*)d_in[8];
    const float* bih = (const float*)d_in[9];
    const float* bhh = (const float*)d_in[10];
    const float* Wo  = (const float*)d_in[11];
    const float* bo  = (const float*)d_in[12];
    float* out = (float*)d_out;

    cudaFuncSetAttribute(att_step, cudaFuncAttributeMaxDynamicSharedMemorySize, ATT_SMEM_BYTES);

    prep_pt<<<256, 256>>>(Wa, Ua);
    prep_vec<<<1, 256>>>(ba, Ua);
    prep_pack<<<KP, 256>>>(Wih, Whh, bih, bhh);

    for (int step = 0; step <= NSTEP; step++){
        att_step<<<B, 256, ATT_SMEM_BYTES>>>(enc, eh, ec, Wo, bo, out, step, step == NSTEP);
        if (step < NSTEP){
            gates_gemm<<<dim3(16, 4, 8), 256>>>();
        }
    }
}

// round 8
// speedup vs baseline: 1.2990x; 1.2990x over previous
#include <cuda_runtime.h>
#include <cuda_fp16.h>
#include <math.h>

// Problem constants
#define B   256
#define S   512
#define H   256
#define OUT 3
#define NSTEP 64
#define G4  1024          // 4*H
#define INW 259           // OUT + H
#define KP  528           // padded K (515 -> 33 tiles of 16)
#define NSPLIT 8

#define PRED_SZ (B*NSTEP*OUT)          // 49152
#define HID_OFF PRED_SZ                // 49152
#define ATTN_OFF (PRED_SZ + B*H)       // 114688

// ---------------- scratch (device globals; no allocation) ----------------
__device__ float  g_P[H*H];        // P row-major: P[h*H + j] = sum_g Ua[g,h]*Wa[g,j]
__device__ float  g_q[H];          // Ua^T @ ba
__device__ float  g_Wc[KP*G4];     // packed weights, k-major: Wc[k*1024 + r]
__device__ float  g_bias[G4];      // b_ih + b_hh
__device__ float  g_XT[KP*B];      // X^T: rows 0..255 ctx, 256..511 h, 512..514 x_in, rest 0
__device__ float  g_c[B*H];        // cell state
__device__ float  g_gates[NSPLIT][B*G4]; // K-split partial gate buffers, layout [b*1024 + r]
__device__ __half g_enc16[(size_t)B*S*H]; // fp16 copy of encoder_outputs (64 MB, L2-resident)

// ---------------- helpers ----------------
__device__ __forceinline__ float sigmoidf_(float x){ return 1.f/(1.f+expf(-x)); }
__device__ __forceinline__ float dot4(float4 a, float4 b){
    return a.x*b.x + a.y*b.y + a.z*b.z + a.w*b.w;
}

// ---------------- precompute 0: enc -> fp16 ----------------
// grid 16384 x 256: thread t converts elements [8t, 8t+8)
__global__ void __launch_bounds__(256) prep_enc(const float* __restrict__ enc){
    size_t t = (size_t)blockIdx.x*256 + threadIdx.x;
    const float4* s4 = (const float4*)enc;
    float4 a = s4[2*t], b = s4[2*t + 1];
    union { uint4 u; __half2 h[4]; } pack;
    pack.h[0] = __float22half2_rn(make_float2(a.x, a.y));
    pack.h[1] = __float22half2_rn(make_float2(a.z, a.w));
    pack.h[2] = __float22half2_rn(make_float2(b.x, b.y));
    pack.h[3] = __float22half2_rn(make_float2(b.z, b.w));
    *(uint4*)&g_enc16[t*8] = pack.u;
}

// ---------------- precompute 1a: P (row-major) ----------------
__global__ void __launch_bounds__(256) prep_pt(const float* __restrict__ Wa,
                                               const float* __restrict__ Ua){
    int j = blockIdx.x, h = threadIdx.x;
    float acc = 0.f;
    for (int g = 0; g < H; g++) acc += Ua[g*H + h] * Wa[g*H + j];
    g_P[h*H + j] = acc;
}

// ---------------- precompute 1b: q ----------------
__global__ void __launch_bounds__(256) prep_vec(const float* __restrict__ ba,
                                                const float* __restrict__ Ua){
    int h = threadIdx.x;
    float a = 0.f;
    for (int g = 0; g < H; g++) a += Ua[g*H + h] * ba[g];
    g_q[h] = a;
}

// ---------------- precompute 2: pack weights + bias + zero pads ----------------
__global__ void __launch_bounds__(256) prep_pack(const float* __restrict__ W_ih,
                                                 const float* __restrict__ W_hh,
                                                 const float* __restrict__ b_ih,
                                                 const float* __restrict__ b_hh){
    int k = blockIdx.x, t = threadIdx.x;
    #pragma unroll
    for (int m = 0; m < 4; m++){
        int r = t + m*256;
        float v;
        if (k < 256)      v = W_ih[r*INW + 3 + k];       // ctx part
        else if (k < 512) v = W_hh[r*H + (k - 256)];     // h part
        else if (k < 515) v = W_ih[r*INW + (k - 512)];   // x_in part
        else              v = 0.f;                       // pad
        g_Wc[k*G4 + r] = v;
    }
    if (k >= 515) g_XT[k*B + t] = 0.f;                   // zero pad rows of X^T
    if (k < 4){
        int r = k*256 + t;
        g_bias[r] = b_ih[r] + b_hh[r];
    }
}

// ---------------- ATT kernel ----------------
// grid = 256 (one block per batch), 256 threads = 8 warps, 2 blocks/SM.
// Warp-private online softmax over fp16 enc (L2-resident), 4 rows/iter,
// register double-buffer prefetch. Zero barriers in the streaming loop.
// Lane owns h = 8*lane .. 8*lane+7.
__global__ void __launch_bounds__(256, 2) att_step(const float* __restrict__ eh,
                                                   const float* __restrict__ ec,
                                                   const float* __restrict__ Wo,
                                                   const float* __restrict__ bo,
                                                   float* __restrict__ out,
                                                   int step, int last){
    __shared__ __align__(16) float scores[S];     // 512
    __shared__ __align__(16) float ctxbuf[8*H];   // 2048
    __shared__ __align__(16) float hsm[H];        // 256
    __shared__ __align__(16) float vqsm[H];       // 256
    __shared__ float red[32];
    __shared__ float mbuf[8], dbuf[8];

    const int tid  = threadIdx.x;
    const int w    = tid >> 5;           // warp 0..7
    const int lane = tid & 31;
    const int b    = blockIdx.x;

    // ---- Phase 0: LSTM cell ----
    float h;
    if (step == 0){
        h = eh[b*H + tid];
        g_c[b*H + tid] = ec[b*H + tid];
        if (tid < 3) g_XT[(512 + tid)*B + b] = 0.f;   // x_in = SOS = 0
    } else {
        float zi = 0.f, zf = 0.f, zg = 0.f, zo = 0.f;
        #pragma unroll
        for (int z = 0; z < NSPLIT; z++){
            const float* G = g_gates[z] + b*G4 + tid;
            zi += G[0]; zf += G[256]; zg += G[512]; zo += G[768];
        }
        float co = g_c[b*H + tid];
        float cn = sigmoidf_(zf)*co + sigmoidf_(zi)*tanhf(zg);
        h = sigmoidf_(zo)*tanhf(cn);
        g_c[b*H + tid] = cn;
    }
    hsm[tid] = h;
    if (!last) g_XT[(256 + tid)*B + b] = h;
    __syncthreads();

    // ---- pred = Wo @ h + bo  (previous step's output; feeds x_in) ----
    if (step > 0){
        float v0 = Wo[tid] * h, v1 = Wo[256 + tid] * h, v2 = Wo[512 + tid] * h;
        #pragma unroll
        for (int o = 16; o > 0; o >>= 1){
            v0 += __shfl_down_sync(0xffffffffu, v0, o);
            v1 += __shfl_down_sync(0xffffffffu, v1, o);
            v2 += __shfl_down_sync(0xffffffffu, v2, o);
        }
        if (lane == 0){ red[w] = v0; red[8 + w] = v1; red[16 + w] = v2; }
        __syncthreads();
        if (tid == 0){
            float a0 = 0.f, a1 = 0.f, a2 = 0.f;
            #pragma unroll
            for (int i = 0; i < 8; i++){ a0 += red[i]; a1 += red[8+i]; a2 += red[16+i]; }
            float p0 = a0 + bo[0], p1 = a1 + bo[1], p2 = a2 + bo[2];
            size_t po = (size_t)b*(NSTEP*OUT) + (step - 1)*OUT;
            out[po] = p0; out[po+1] = p1; out[po+2] = p2;
            if (!last){
                g_XT[512*B + b] = p0;
                g_XT[513*B + b] = p1;
                g_XT[514*B + b] = p2;
            }
        }
    }

    if (last){
        out[HID_OFF + b*H + tid] = h;   // decoder_hidden
        return;
    }

    // ---- vq = P @ h + q  (per-thread row of P, vectorized LDG.128) ----
    {
        float a0 = g_q[tid], a1 = 0.f, a2 = 0.f, a3 = 0.f;
        const float4* Pr = (const float4*)(g_P + tid*H);
        const float4* hv4 = (const float4*)hsm;
        #pragma unroll 8
        for (int j4 = 0; j4 < 64; j4 += 4){
            a0 += dot4(Pr[j4],   hv4[j4]);
            a1 += dot4(Pr[j4+1], hv4[j4+1]);
            a2 += dot4(Pr[j4+2], hv4[j4+2]);
            a3 += dot4(Pr[j4+3], hv4[j4+3]);
        }
        vqsm[tid] = (a0 + a1) + (a2 + a3);
    }
    __syncthreads();

    // per-lane vq: elems 8*lane .. 8*lane+7
    float vq8[8];
    {
        float4 va = *(const float4*)&vqsm[8*lane];
        float4 vb = *(const float4*)&vqsm[8*lane + 4];
        vq8[0]=va.x; vq8[1]=va.y; vq8[2]=va.z; vq8[3]=va.w;
        vq8[4]=vb.x; vq8[5]=vb.y; vq8[6]=vb.z; vq8[7]=vb.w;
    }

    // ---- streaming loop: warp w owns rows [w*64, w*64+64), 16 iters x 4 rows ----
    // row = 256 halves = 512B; lane loads 16B (8 halves) per row.
    const uint4* rowu = (const uint4*)(g_enc16 + (size_t)b*S*H + (size_t)(w*64)*H);

    uint4 U[2][4];
    #pragma unroll
    for (int r = 0; r < 4; r++) U[0][r] = rowu[r*32 + lane];

    float m = -1e30f, d = 0.f;
    float ctx[8];
    #pragma unroll
    for (int j = 0; j < 8; j++) ctx[j] = 0.f;

    #pragma unroll
    for (int c = 0; c < 16; c++){
        const int cur = c & 1, nxt = cur ^ 1;
        if (c < 15){
            const uint4* nb = rowu + (c+1)*128;
            #pragma unroll
            for (int r = 0; r < 4; r++) U[nxt][r] = nb[r*32 + lane];
        }

        // convert + score
        float f[4][8];
        float p[4];
        #pragma unroll
        for (int r = 0; r < 4; r++){
            const __half2* h2 = (const __half2*)&U[cur][r];
            #pragma unroll
            for (int k = 0; k < 4; k++){
                float2 t = __half22float2(h2[k]);
                f[r][2*k]   = t.x;
                f[r][2*k+1] = t.y;
            }
            float acc = 0.f;
            #pragma unroll
            for (int j = 0; j < 8; j++) acc += f[r][j] * vq8[j];
            p[r] = acc;
        }
        #pragma unroll
        for (int o = 16; o > 0; o >>= 1){
            p[0] += __shfl_xor_sync(0xffffffffu, p[0], o);
            p[1] += __shfl_xor_sync(0xffffffffu, p[1], o);
            p[2] += __shfl_xor_sync(0xffffffffu, p[2], o);
            p[3] += __shfl_xor_sync(0xffffffffu, p[3], o);
        }
        if (lane == 0) *(float4*)&scores[w*64 + c*4] = make_float4(p[0], p[1], p[2], p[3]);

        float mn = fmaxf(m, fmaxf(fmaxf(p[0], p[1]), fmaxf(p[2], p[3])));
        float rs = __expf(m - mn);
        float e0 = __expf(p[0] - mn);
        float e1 = __expf(p[1] - mn);
        float e2 = __expf(p[2] - mn);
        float e3 = __expf(p[3] - mn);
        d = d*rs + (e0 + e1) + (e2 + e3);
        #pragma unroll
        for (int j = 0; j < 8; j++)
            ctx[j] = ctx[j]*rs + e0*f[0][j] + e1*f[1][j] + e2*f[2][j] + e3*f[3][j];
        m = mn;
    }

    // ---- merge 8 warp-private states ----
    {
        float4 ca = make_float4(ctx[0], ctx[1], ctx[2], ctx[3]);
        float4 cb = make_float4(ctx[4], ctx[5], ctx[6], ctx[7]);
        *(float4*)&ctxbuf[w*H + 8*lane]     = ca;
        *(float4*)&ctxbuf[w*H + 8*lane + 4] = cb;
    }
    if (lane == 0){ mbuf[w] = m; dbuf[w] = d; }
    __syncthreads();

    float M = -1e30f;
    #pragma unroll
    for (int i = 0; i < 8; i++) M = fmaxf(M, mbuf[i]);
    float D = 0.f;
    float ew[8];
    #pragma unroll
    for (int i = 0; i < 8; i++){ ew[i] = __expf(mbuf[i] - M); D += dbuf[i] * ew[i]; }
    float inv = 1.f / D;

    {
        float cx = 0.f;
        #pragma unroll
        for (int i = 0; i < 8; i++) cx += ctxbuf[i*H + tid] * ew[i];
        g_XT[tid*B + b] = cx * inv;
    }
    size_t abase = (size_t)ATTN_OFF + ((size_t)b*NSTEP + step)*S;
    out[abase + tid]       = __expf(scores[tid]       - M) * inv;
    out[abase + tid + 256] = __expf(scores[tid + 256] - M) * inv;
}

// ---------------- gates GEMM: C[r,b] = sum_k Wc[k,r] * XT[k,b], 8-way K split ----------------
// grid (16, 4, 8): 64x64 output tiles, z = K split. 256 threads, 4x4 microtile.
__global__ void __launch_bounds__(256) gates_gemm(){
    const int rt = blockIdx.x, bt = blockIdx.y, z = blockIdx.z;
    const int starts[9] = {0, 5, 9, 13, 17, 21, 25, 29, 33};
    const int t0 = starts[z], t1 = starts[z+1];

    __shared__ float As[2][16][68];
    __shared__ float Bs[2][16][68];

    const int tid = threadIdx.x;
    const int tx = tid & 15, ty = tid >> 4;
    const int lk = tid >> 4, lx = (tid & 15) * 4;

    float4 pa, pb;
    {
        int k = t0*16 + lk;
        pa = *(const float4*)&g_Wc[k*G4 + rt*64 + lx];
        pb = *(const float4*)&g_XT[k*B  + bt*64 + lx];
    }
    *(float4*)&As[0][lk][lx] = pa;
    *(float4*)&Bs[0][lk][lx] = pb;

    float acc[4][4];
    #pragma unroll
    for (int i = 0; i < 4; i++)
        #pragma unroll
        for (int j = 0; j < 4; j++) acc[i][j] = 0.f;

    const int nt = t1 - t0;
    for (int it = 0; it < nt; it++){
        __syncthreads();
        if (it + 1 < nt){
            int k = (t0 + it + 1)*16 + lk;
            pa = *(const float4*)&g_Wc[k*G4 + rt*64 + lx];
            pb = *(const float4*)&g_XT[k*B  + bt*64 + lx];
        }
        int cur = it & 1;
        #pragma unroll
        for (int kk = 0; kk < 16; kk++){
            float4 fa = *(float4*)&As[cur][kk][ty*4];
            float4 fb = *(float4*)&Bs[cur][kk][tx*4];
            acc[0][0] += fa.x*fb.x; acc[0][1] += fa.x*fb.y; acc[0][2] += fa.x*fb.z; acc[0][3] += fa.x*fb.w;
            acc[1][0] += fa.y*fb.x; acc[1][1] += fa.y*fb.y; acc[1][2] += fa.y*fb.z; acc[1][3] += fa.y*fb.w;
            acc[2][0] += fa.z*fb.x; acc[2][1] += fa.z*fb.y; acc[2][2] += fa.z*fb.z; acc[2][3] += fa.z*fb.w;
            acc[3][0] += fa.w*fb.x; acc[3][1] += fa.w*fb.y; acc[3][2] += fa.w*fb.z; acc[3][3] += fa.w*fb.w;
        }
        if (it + 1 < nt){
            int nxt = cur ^ 1;
            *(float4*)&As[nxt][lk][lx] = pa;
            *(float4*)&Bs[nxt][lk][lx] = pb;
        }
    }

    float* G = g_gates[z];
    const int r0 = rt*64 + ty*4;
    const int b0 = bt*64 + tx*4;
    #pragma unroll
    for (int j = 0; j < 4; j++){
        float4 v = make_float4(acc[0][j], acc[1][j], acc[2][j], acc[3][j]);
        if (z == 0){
            v.x += g_bias[r0];     v.y += g_bias[r0 + 1];
            v.z += g_bias[r0 + 2]; v.w += g_bias[r0 + 3];
        }
        *(float4*)&G[(size_t)(b0 + j)*G4 + r0] = v;
    }
}

// ---------------- launch ----------------
extern "C" void kernel_launch(void* const* d_in, const int* in_sizes, int n_in,
                              void* d_out, int out_size){
    const float* enc = (const float*)d_in[0];
    const float* eh  = (const float*)d_in[1];
    const float* ec  = (const float*)d_in[2];
    const float* Wa  = (const float*)d_in[3];
    const float* ba  = (const float*)d_in[4];
    const float* Ua  = (const float*)d_in[5];
    const float* Wih = (const float*)d_in[7];
    const float* Whh = (const float*)d_in[8];
    const float* bih = (const float*)d_in[9];
    const float* bhh = (const float*)d_in[10];
    const float* Wo  = (const float*)d_in[11];
    const float* bo  = (const float*)d_in[12];
    float* out = (float*)d_out;

    prep_enc<<<16384, 256>>>(enc);
    prep_pt<<<256, 256>>>(Wa, Ua);
    prep_vec<<<1, 256>>>(ba, Ua);
    prep_pack<<<KP, 256>>>(Wih, Whh, bih, bhh);

    for (int step = 0; step <= NSTEP; step++){
        att_step<<<B, 256>>>(eh, ec, Wo, bo, out, step, step == NSTEP);
        if (step < NSTEP){
            gates_gemm<<<dim3(16, 4, 8), 256>>>();
        }
    }
}

// round 10
// speedup vs baseline: 1.3056x; 1.0051x over previous
#include <cuda_runtime.h>
#include <cuda_fp16.h>
#include <math.h>

// Problem constants
#define B   256
#define S   512
#define H   256
#define OUT 3
#define NSTEP 64
#define G4  1024          // 4*H
#define INW 259           // OUT + H
#define KP  528           // padded K (515 -> 33 tiles of 16)
#define NSPLIT 8

#define PRED_SZ (B*NSTEP*OUT)          // 49152
#define HID_OFF PRED_SZ                // 49152
#define ATTN_OFF (PRED_SZ + B*H)       // 114688

// ---------------- scratch (device globals; no allocation) ----------------
__device__ float  g_P[H*H];        // P row-major: P[h*H + j] = sum_g Ua[g,h]*Wa[g,j]
__device__ float  g_q[H];          // Ua^T @ ba
__device__ float  g_Wc[KP*G4];     // packed weights, k-major: Wc[k*1024 + r]
__device__ float  g_bias[G4];      // b_ih + b_hh
__device__ float  g_XT[KP*B];      // X^T: rows 0..255 ctx, 256..511 h, 512..514 x_in, rest 0
__device__ float  g_c[B*H];        // cell state
__device__ float  g_gates[NSPLIT][B*G4]; // K-split partial gate buffers, layout [b*1024 + r]
__device__ __half g_enc16[(size_t)B*S*H]; // fp16 copy of encoder_outputs (64 MB, L2 evict_last)

// ---------------- helpers ----------------
__device__ __forceinline__ float sigmoidf_(float x){ return 1.f/(1.f+expf(-x)); }
__device__ __forceinline__ float dot4(float4 a, float4 b){
    return a.x*b.x + a.y*b.y + a.z*b.z + a.w*b.w;
}
// L2 evict_last access policy (createpolicy + cache_hint works for any width)
__device__ __forceinline__ unsigned long long mkpolicy_el(){
    unsigned long long pol;
    asm("createpolicy.fractional.L2::evict_last.b64 %0, 1.0;" : "=l"(pol));
    return pol;
}
__device__ __forceinline__ uint4 ldg_el(const uint4* p, unsigned long long pol){
    uint4 v;
    asm("ld.global.nc.L2::cache_hint.v4.u32 {%0,%1,%2,%3}, [%4], %5;"
        : "=r"(v.x), "=r"(v.y), "=r"(v.z), "=r"(v.w) : "l"(p), "l"(pol));
    return v;
}
__device__ __forceinline__ void stg_el(uint4* p, uint4 v, unsigned long long pol){
    asm volatile("st.global.L2::cache_hint.v4.u32 [%0], {%1,%2,%3,%4}, %5;"
                 :: "l"(p), "r"(v.x), "r"(v.y), "r"(v.z), "r"(v.w), "l"(pol) : "memory");
}

// ---------------- precompute 0: enc -> fp16 (evict_last stores) ----------------
// grid 16384 x 256: thread t converts elements [8t, 8t+8)
__global__ void __launch_bounds__(256) prep_enc(const float* __restrict__ enc){
    size_t t = (size_t)blockIdx.x*256 + threadIdx.x;
    const float4* s4 = (const float4*)enc;
    float4 a = s4[2*t], b = s4[2*t + 1];
    union { uint4 u; __half2 h[4]; } pack;
    pack.h[0] = __float22half2_rn(make_float2(a.x, a.y));
    pack.h[1] = __float22half2_rn(make_float2(a.z, a.w));
    pack.h[2] = __float22half2_rn(make_float2(b.x, b.y));
    pack.h[3] = __float22half2_rn(make_float2(b.z, b.w));
    stg_el((uint4*)&g_enc16[t*8], pack.u, mkpolicy_el());
}

// ---------------- precompute 1: P (row-major) + q ----------------
__global__ void __launch_bounds__(256) prep_pt(const float* __restrict__ Wa,
                                               const float* __restrict__ ba,
                                               const float* __restrict__ Ua){
    int j = blockIdx.x, h = threadIdx.x;
    float acc = 0.f;
    for (int g = 0; g < H; g++) acc += Ua[g*H + h] * Wa[g*H + j];
    g_P[h*H + j] = acc;
    if (j == 0){
        float a = 0.f;
        for (int g = 0; g < H; g++) a += Ua[g*H + h] * ba[g];
        g_q[h] = a;
    }
}

// ---------------- precompute 2: pack weights + bias + zero pads ----------------
__global__ void __launch_bounds__(256) prep_pack(const float* __restrict__ W_ih,
                                                 const float* __restrict__ W_hh,
                                                 const float* __restrict__ b_ih,
                                                 const float* __restrict__ b_hh){
    int k = blockIdx.x, t = threadIdx.x;
    #pragma unroll
    for (int m = 0; m < 4; m++){
        int r = t + m*256;
        float v;
        if (k < 256)      v = W_ih[r*INW + 3 + k];       // ctx part
        else if (k < 512) v = W_hh[r*H + (k - 256)];     // h part
        else if (k < 515) v = W_ih[r*INW + (k - 512)];   // x_in part
        else              v = 0.f;                       // pad
        g_Wc[k*G4 + r] = v;
    }
    if (k >= 515) g_XT[k*B + t] = 0.f;                   // zero pad rows of X^T
    if (k < 4){
        int r = k*256 + t;
        g_bias[r] = b_ih[r] + b_hh[r];
    }
}

// ---------------- ATT kernel ----------------
// grid = 256 (one block per batch), 256 threads = 8 warps, 2 blocks/SM.
// Warp-private online softmax over fp16 enc (L2 evict_last), 4 rows/iter,
// register double-buffer prefetch. Zero barriers in the streaming loop.
__global__ void __launch_bounds__(256, 2) att_step(const float* __restrict__ eh,
                                                   const float* __restrict__ ec,
                                                   const float* __restrict__ Wo,
                                                   const float* __restrict__ bo,
                                                   float* __restrict__ out,
                                                   int step, int last){
    __shared__ __align__(16) float scores[S];     // 512
    __shared__ __align__(16) float ctxbuf[8*H];   // 2048
    __shared__ __align__(16) float hsm[H];        // 256
    __shared__ __align__(16) float vqsm[H];       // 256
    __shared__ float red[32];
    __shared__ float mbuf[8], dbuf[8];

    const int tid  = threadIdx.x;
    const int w    = tid >> 5;           // warp 0..7
    const int lane = tid & 31;
    const int b    = blockIdx.x;

    // ---- Phase 0: LSTM cell ----
    float h;
    if (step == 0){
        h = eh[b*H + tid];
        g_c[b*H + tid] = ec[b*H + tid];
        if (tid < 3) g_XT[(512 + tid)*B + b] = 0.f;   // x_in = SOS = 0
    } else {
        float zi = 0.f, zf = 0.f, zg = 0.f, zo = 0.f;
        #pragma unroll
        for (int z = 0; z < NSPLIT; z++){
            const float* G = g_gates[z] + b*G4 + tid;
            zi += G[0]; zf += G[256]; zg += G[512]; zo += G[768];
        }
        float co = g_c[b*H + tid];
        float cn = sigmoidf_(zf)*co + sigmoidf_(zi)*tanhf(zg);
        h = sigmoidf_(zo)*tanhf(cn);
        g_c[b*H + tid] = cn;
    }
    hsm[tid] = h;
    if (!last) g_XT[(256 + tid)*B + b] = h;
    __syncthreads();

    // ---- pred = Wo @ h + bo  (previous step's output; feeds x_in) ----
    if (step > 0){
        float v0 = Wo[tid] * h, v1 = Wo[256 + tid] * h, v2 = Wo[512 + tid] * h;
        #pragma unroll
        for (int o = 16; o > 0; o >>= 1){
            v0 += __shfl_down_sync(0xffffffffu, v0, o);
            v1 += __shfl_down_sync(0xffffffffu, v1, o);
            v2 += __shfl_down_sync(0xffffffffu, v2, o);
        }
        if (lane == 0){ red[w] = v0; red[8 + w] = v1; red[16 + w] = v2; }
        __syncthreads();
        if (tid == 0){
            float a0 = 0.f, a1 = 0.f, a2 = 0.f;
            #pragma unroll
            for (int i = 0; i < 8; i++){ a0 += red[i]; a1 += red[8+i]; a2 += red[16+i]; }
            float p0 = a0 + bo[0], p1 = a1 + bo[1], p2 = a2 + bo[2];
            size_t po = (size_t)b*(NSTEP*OUT) + (step - 1)*OUT;
            out[po] = p0; out[po+1] = p1; out[po+2] = p2;
            if (!last){
                g_XT[512*B + b] = p0;
                g_XT[513*B + b] = p1;
                g_XT[514*B + b] = p2;
            }
        }
    }

    if (last){
        out[HID_OFF + b*H + tid] = h;   // decoder_hidden
        return;
    }

    // ---- vq = P @ h + q  (per-thread row of P, vectorized LDG.128) ----
    {
        float a0 = g_q[tid], a1 = 0.f, a2 = 0.f, a3 = 0.f;
        const float4* Pr = (const float4*)(g_P + tid*H);
        const float4* hv4 = (const float4*)hsm;
        #pragma unroll 8
        for (int j4 = 0; j4 < 64; j4 += 4){
            a0 += dot4(Pr[j4],   hv4[j4]);
            a1 += dot4(Pr[j4+1], hv4[j4+1]);
            a2 += dot4(Pr[j4+2], hv4[j4+2]);
            a3 += dot4(Pr[j4+3], hv4[j4+3]);
        }
        vqsm[tid] = (a0 + a1) + (a2 + a3);
    }
    __syncthreads();

    // per-lane vq: elems 8*lane .. 8*lane+7
    float vq8[8];
    {
        float4 va = *(const float4*)&vqsm[8*lane];
        float4 vb = *(const float4*)&vqsm[8*lane + 4];
        vq8[0]=va.x; vq8[1]=va.y; vq8[2]=va.z; vq8[3]=va.w;
        vq8[4]=vb.x; vq8[5]=vb.y; vq8[6]=vb.z; vq8[7]=vb.w;
    }

    // ---- streaming loop: warp w owns rows [w*64, w*64+64), 16 iters x 4 rows ----
    // row = 256 halves = 512B; lane loads 16B (8 halves) per row, evict_last.
    const unsigned long long pol = mkpolicy_el();
    const uint4* rowu = (const uint4*)(g_enc16 + (size_t)b*S*H + (size_t)(w*64)*H);

    uint4 U[2][4];
    #pragma unroll
    for (int r = 0; r < 4; r++) U[0][r] = ldg_el(rowu + r*32 + lane, pol);

    float m = -1e30f, d = 0.f;
    float ctx[8];
    #pragma unroll
    for (int j = 0; j < 8; j++) ctx[j] = 0.f;

    #pragma unroll
    for (int c = 0; c < 16; c++){
        const int cur = c & 1, nxt = cur ^ 1;
        if (c < 15){
            const uint4* nb = rowu + (c+1)*128;
            #pragma unroll
            for (int r = 0; r < 4; r++) U[nxt][r] = ldg_el(nb + r*32 + lane, pol);
        }

        // convert + score
        float f[4][8];
        float p[4];
        #pragma unroll
        for (int r = 0; r < 4; r++){
            const __half2* h2 = (const __half2*)&U[cur][r];
            #pragma unroll
            for (int k = 0; k < 4; k++){
                float2 t = __half22float2(h2[k]);
                f[r][2*k]   = t.x;
                f[r][2*k+1] = t.y;
            }
            float acc = 0.f;
            #pragma unroll
            for (int j = 0; j < 8; j++) acc += f[r][j] * vq8[j];
            p[r] = acc;
        }
        #pragma unroll
        for (int o = 16; o > 0; o >>= 1){
            p[0] += __shfl_xor_sync(0xffffffffu, p[0], o);
            p[1] += __shfl_xor_sync(0xffffffffu, p[1], o);
            p[2] += __shfl_xor_sync(0xffffffffu, p[2], o);
            p[3] += __shfl_xor_sync(0xffffffffu, p[3], o);
        }
        if (lane == 0) *(float4*)&scores[w*64 + c*4] = make_float4(p[0], p[1], p[2], p[3]);

        float mn = fmaxf(m, fmaxf(fmaxf(p[0], p[1]), fmaxf(p[2], p[3])));
        float rs = __expf(m - mn);
        float e0 = __expf(p[0] - mn);
        float e1 = __expf(p[1] - mn);
        float e2 = __expf(p[2] - mn);
        float e3 = __expf(p[3] - mn);
        d = d*rs + (e0 + e1) + (e2 + e3);
        #pragma unroll
        for (int j = 0; j < 8; j++)
            ctx[j] = ctx[j]*rs + e0*f[0][j] + e1*f[1][j] + e2*f[2][j] + e3*f[3][j];
        m = mn;
    }

    // ---- merge 8 warp-private states ----
    {
        float4 ca = make_float4(ctx[0], ctx[1], ctx[2], ctx[3]);
        float4 cb = make_float4(ctx[4], ctx[5], ctx[6], ctx[7]);
        *(float4*)&ctxbuf[w*H + 8*lane]     = ca;
        *(float4*)&ctxbuf[w*H + 8*lane + 4] = cb;
    }
    if (lane == 0){ mbuf[w] = m; dbuf[w] = d; }
    __syncthreads();

    float M = -1e30f;
    #pragma unroll
    for (int i = 0; i < 8; i++) M = fmaxf(M, mbuf[i]);
    float D = 0.f;
    float ew[8];
    #pragma unroll
    for (int i = 0; i < 8; i++){ ew[i] = __expf(mbuf[i] - M); D += dbuf[i] * ew[i]; }
    float inv = 1.f / D;

    {
        float cx = 0.f;
        #pragma unroll
        for (int i = 0; i < 8; i++) cx += ctxbuf[i*H + tid] * ew[i];
        g_XT[tid*B + b] = cx * inv;
    }
    size_t abase = (size_t)ATTN_OFF + ((size_t)b*NSTEP + step)*S;
    out[abase + tid]       = __expf(scores[tid]       - M) * inv;
    out[abase + tid + 256] = __expf(scores[tid + 256] - M) * inv;
}

// ---------------- gates GEMM: C[r,b] = sum_k Wc[k,r] * XT[k,b], 8-way K split ----------------
// grid (16, 4, 8): 64x64 output tiles, z = K split. 256 threads, 4x4 microtile.
__global__ void __launch_bounds__(256) gates_gemm(){
    const int rt = blockIdx.x, bt = blockIdx.y, z = blockIdx.z;
    const int starts[9] = {0, 5, 9, 13, 17, 21, 25, 29, 33};
    const int t0 = starts[z], t1 = starts[z+1];

    __shared__ float As[2][16][68];
    __shared__ float Bs[2][16][68];

    const int tid = threadIdx.x;
    const int tx = tid & 15, ty = tid >> 4;
    const int lk = tid >> 4, lx = (tid & 15) * 4;

    float4 pa, pb;
    {
        int k = t0*16 + lk;
        pa = *(const float4*)&g_Wc[k*G4 + rt*64 + lx];
        pb = *(const float4*)&g_XT[k*B  + bt*64 + lx];
    }
    *(float4*)&As[0][lk][lx] = pa;
    *(float4*)&Bs[0][lk][lx] = pb;

    float acc[4][4];
    #pragma unroll
    for (int i = 0; i < 4; i++)
        #pragma unroll
        for (int j = 0; j < 4; j++) acc[i][j] = 0.f;

    const int nt = t1 - t0;
    for (int it = 0; it < nt; it++){
        __syncthreads();
        if (it + 1 < nt){
            int k = (t0 + it + 1)*16 + lk;
            pa = *(const float4*)&g_Wc[k*G4 + rt*64 + lx];
            pb = *(const float4*)&g_XT[k*B  + bt*64 + lx];
        }
        int cur = it & 1;
        #pragma unroll
        for (int kk = 0; kk < 16; kk++){
            float4 fa = *(float4*)&As[cur][kk][ty*4];
            float4 fb = *(float4*)&Bs[cur][kk][tx*4];
            acc[0][0] += fa.x*fb.x; acc[0][1] += fa.x*fb.y; acc[0][2] += fa.x*fb.z; acc[0][3] += fa.x*fb.w;
            acc[1][0] += fa.y*fb.x; acc[1][1] += fa.y*fb.y; acc[1][2] += fa.y*fb.z; acc[1][3] += fa.y*fb.w;
            acc[2][0] += fa.z*fb.x; acc[2][1] += fa.z*fb.y; acc[2][2] += fa.z*fb.z; acc[2][3] += fa.z*fb.w;
            acc[3][0] += fa.w*fb.x; acc[3][1] += fa.w*fb.y; acc[3][2] += fa.w*fb.z; acc[3][3] += fa.w*fb.w;
        }
        if (it + 1 < nt){
            int nxt = cur ^ 1;
            *(float4*)&As[nxt][lk][lx] = pa;
            *(float4*)&Bs[nxt][lk][lx] = pb;
        }
    }

    float* G = g_gates[z];
    const int r0 = rt*64 + ty*4;
    const int b0 = bt*64 + tx*4;
    #pragma unroll
    for (int j = 0; j < 4; j++){
        float4 v = make_float4(acc[0][j], acc[1][j], acc[2][j], acc[3][j]);
        if (z == 0){
            v.x += g_bias[r0];     v.y += g_bias[r0 + 1];
            v.z += g_bias[r0 + 2]; v.w += g_bias[r0 + 3];
        }
        *(float4*)&G[(size_t)(b0 + j)*G4 + r0] = v;
    }
}

// ---------------- launch ----------------
extern "C" void kernel_launch(void* const* d_in, const int* in_sizes, int n_in,
                              void* d_out, int out_size){
    const float* enc = (const float*)d_in[0];
    const float* eh  = (const float*)d_in[1];
    const float* ec  = (const float*)d_in[2];
    const float* Wa  = (const float*)d_in[3];
    const float* ba  = (const float*)d_in[4];
    const float* Ua  = (const float*)d_in[5];
    const float* Wih = (const float*)d_in[7];
    const float* Whh = (const float*)d_in[8];
    const float* bih = (const float*)d_in[9];
    const float* bhh = (const float*)d_in[10];
    const float* Wo  = (const float*)d_in[11];
    const float* bo  = (const float*)d_in[12];
    float* out = (float*)d_out;

    prep_enc<<<16384, 256>>>(enc);
    prep_pt<<<256, 256>>>(Wa, ba, Ua);
    prep_pack<<<KP, 256>>>(Wih, Whh, bih, bhh);

    for (int step = 0; step <= NSTEP; step++){
        att_step<<<B, 256>>>(eh, ec, Wo, bo, out, step, step == NSTEP);
        if (step < NSTEP){
            gates_gemm<<<dim3(16, 4, 8), 256>>>();
        }
    }
}